// round 1
// baseline (speedup 1.0000x reference)
#include <cuda_runtime.h>

// ============================================================================
// PhasorTransformer: 16384 rows x 2048.
// Per row: z=exp(i(x+w00)); [FFT; *m_b] x3 ; final "FFT" only needs bin 0 -> sum.
// norm="ortho" scalings dropped (angle-invariant). Output = triangular wrap of
// atan2(sum) + w[3,1,0].
//
// FFT2048 = radix 16*16*8, 128 threads/row, 16 complex regs/thread,
// 3 shared-memory passes, natural order maintained at every FFT boundary
// (scramble undone for free in the pass-3 scatter).
// ============================================================================

#define NFFT 2048
#define TPB  128
#define PADI(i) ((i) + ((i) >> 5))   // +1 float pad per 32 -> bank spread

__device__ float2 g_m1[NFFT];
__device__ float2 g_m2[NFFT];
__device__ float2 g_m3[NFFT];
__device__ float2 g_tw[NFFT];   // exp(-2*pi*i*k/2048), double-precision computed

// ---------------------------------------------------------------- init tables
__global__ void init_tables_kernel(const float* __restrict__ w) {
    int k = blockIdx.x * blockDim.x + threadIdx.x;
    if (k >= NFFT) return;
    double a;
    a = (double)w[2048 + k] + (double)w[4096 + k];       // w01 + w10
    g_m1[k] = make_float2((float)cos(a), (float)sin(a));
    a = (double)w[6144 + k] + (double)w[8192 + k];       // w11 + w20
    g_m2[k] = make_float2((float)cos(a), (float)sin(a));
    a = (double)w[10240 + k] + (double)w[12288 + k];     // w21 + w30
    g_m3[k] = make_float2((float)cos(a), (float)sin(a));
    double t = -6.283185307179586476925286766559 * (double)k / (double)NFFT;
    g_tw[k] = make_float2((float)cos(t), (float)sin(t));
}

// ---------------------------------------------------------------- complex ops
__device__ __forceinline__ float2 cmul(float2 a, float2 b) {
    return make_float2(fmaf(a.x, b.x, -a.y * b.y), fmaf(a.x, b.y, a.y * b.x));
}
__device__ __forceinline__ float2 cadd(float2 a, float2 b) { return make_float2(a.x + b.x, a.y + b.y); }
__device__ __forceinline__ float2 csub(float2 a, float2 b) { return make_float2(a.x - b.x, a.y - b.y); }
__device__ __forceinline__ float2 mulnegi(float2 a) { return make_float2(a.y, -a.x); }   // a * (-i)

// forward DFT4 (w = e^{-2pi i/4} = -i), in place, natural freq order
__device__ __forceinline__ void dft4(float2& a0, float2& a1, float2& a2, float2& a3) {
    float2 t0 = cadd(a0, a2), t1 = csub(a0, a2);
    float2 t2 = cadd(a1, a3), t3 = csub(a1, a3);
    a0 = cadd(t0, t2);
    a2 = csub(t0, t2);
    float2 it3 = mulnegi(t3);
    a1 = cadd(t1, it3);
    a3 = csub(t1, it3);
}

// forward DFT16 (DIF 4x4). Output: X[k1 + 4*k2] resides at v[4*k1 + k2].
__device__ __forceinline__ void dft16(float2 v[16]) {
    const float C1 = 0.92387953251128675f;   // cos(pi/8)
    const float S1 = 0.38268343236508977f;   // sin(pi/8)
    const float R2 = 0.70710678118654752f;
#pragma unroll
    for (int j2 = 0; j2 < 4; j2++)
        dft4(v[j2], v[j2 + 4], v[j2 + 8], v[j2 + 12]);
    // twiddle w16^{j2*k1} on v[j2 + 4*k1]
    v[5]  = cmul(v[5],  make_float2( C1, -S1));  // w^1
    v[9]  = cmul(v[9],  make_float2( R2, -R2));  // w^2
    v[13] = cmul(v[13], make_float2( S1, -C1));  // w^3
    v[6]  = cmul(v[6],  make_float2( R2, -R2));  // w^2
    v[10] = mulnegi(v[10]);                       // w^4
    v[14] = cmul(v[14], make_float2(-R2, -R2));  // w^6
    v[7]  = cmul(v[7],  make_float2( S1, -C1));  // w^3
    v[11] = cmul(v[11], make_float2(-R2, -R2));  // w^6
    v[15] = cmul(v[15], make_float2(-C1,  S1));  // w^9
#pragma unroll
    for (int k1 = 0; k1 < 4; k1++)
        dft4(v[4 * k1], v[4 * k1 + 1], v[4 * k1 + 2], v[4 * k1 + 3]);
}

// forward DFT8 (DIF 4x2): input a[0..7] time order, output o[0..7] natural freq.
__device__ __forceinline__ void dft8(float2* a, float2* o) {
    const float R2 = 0.70710678118654752f;
    dft4(a[0], a[2], a[4], a[6]);
    dft4(a[1], a[3], a[5], a[7]);
    a[3] = cmul(a[3], make_float2(R2, -R2));     // w8^1
    a[5] = mulnegi(a[5]);                         // w8^2
    a[7] = cmul(a[7], make_float2(-R2, -R2));    // w8^3
#pragma unroll
    for (int k1 = 0; k1 < 4; k1++) {
        o[k1]     = cadd(a[2 * k1], a[2 * k1 + 1]);
        o[k1 + 4] = csub(a[2 * k1], a[2 * k1 + 1]);
    }
}

// dft16 + outer twiddle w1^f + store at smem[f*128 + t]  (lane-stride-1 writes)
__device__ __forceinline__ void pass_store(float2 v[16], int t, float2 w1,
                                           float* sre, float* sim) {
    dft16(v);
    constexpr int idx16[16] = {0, 4, 8, 12, 1, 5, 9, 13, 2, 6, 10, 14, 3, 7, 11, 15};
    {
        int a = PADI(t);
        sre[a] = v[0].x; sim[a] = v[0].y;
    }
    float2 wk = w1;
#pragma unroll
    for (int f = 1; f < 16; f++) {
        float2 val = cmul(v[idx16[f]], wk);
        int a = PADI(f * TPB + t);
        sre[a] = val.x; sim[a] = val.y;
        if (f < 15) wk = cmul(wk, w1);
    }
}

__device__ __forceinline__ void load_p1(float2 v[16], int t,
                                        const float* sre, const float* sim) {
#pragma unroll
    for (int j = 0; j < 16; j++) {
        int a = PADI(t + TPB * j);
        v[j] = make_float2(sre[a], sim[a]);
    }
}

__device__ __forceinline__ void load_p2(float2 v[16], int t,
                                        const float* sre, const float* sim) {
    int base = (t >> 3) * TPB + (t & 7);
#pragma unroll
    for (int j = 0; j < 16; j++) {
        int a = PADI(base + 8 * j);
        v[j] = make_float2(sre[a], sim[a]);
    }
}

// pass-2 wrote sub-block q (= b + 16*f) contiguously at [8q .. 8q+7]
__device__ __forceinline__ void load_p3(float2 v[16], int t,
                                        const float* sre, const float* sim) {
#pragma unroll
    for (int i = 0; i < 2; i++) {
        int q = t + TPB * i;
#pragma unroll
        for (int j = 0; j < 8; j++) {
            int a = PADI(q * 8 + j);
            v[8 * i + j] = make_float2(sre[a], sim[a]);
        }
    }
}

// final radix-8, fuse inter-FFT phase multiply, scatter to NATURAL order
__device__ __forceinline__ void p3_store(float2 v[16], int t, const float2* __restrict__ m,
                                         float* sre, float* sim) {
#pragma unroll
    for (int i = 0; i < 2; i++) {
        int q = t + TPB * i;
        float2 o[8];
        dft8(v + 8 * i, o);
#pragma unroll
        for (int d = 0; d < 8; d++) {
            int g = q + 256 * d;                 // global natural index
            float2 val = cmul(o[d], m[g]);
            int a = PADI(g);
            sre[a] = val.x; sim[a] = val.y;
        }
    }
}

// ---------------------------------------------------------------- main kernel
__global__ void __launch_bounds__(TPB)
phasor_kernel(const float* __restrict__ x, const float* __restrict__ w,
              float* __restrict__ out) {
    __shared__ float sre[2112];
    __shared__ float sim[2112];
    const int t = threadIdx.x;

    float2 v[16];

    // ---- FFT #1, pass 1: build z = exp(i(x + w00)) directly in registers
    {
        const float* xr = x + (size_t)blockIdx.x * NFFT;
#pragma unroll
        for (int j = 0; j < 16; j++) {
            int e = t + TPB * j;
            float ph = xr[e] + w[e];             // w00 folded into input phase
            float s, c;
            sincosf(ph, &s, &c);
            v[j] = make_float2(c, s);
        }
    }
    const float2 tw_p1 = g_tw[t];                // e^{-2pi i t/2048}
    const float2 tw_p2 = g_tw[16 * (t & 7)];     // e^{-2pi i j2/128}

    // FFT #1
    pass_store(v, t, tw_p1, sre, sim);  __syncthreads();
    load_p2(v, t, sre, sim);            __syncthreads();
    pass_store(v, t, tw_p2, sre, sim);  __syncthreads();
    load_p3(v, t, sre, sim);            __syncthreads();
    p3_store(v, t, g_m1, sre, sim);     __syncthreads();

    // FFT #2
    load_p1(v, t, sre, sim);            __syncthreads();
    pass_store(v, t, tw_p1, sre, sim);  __syncthreads();
    load_p2(v, t, sre, sim);            __syncthreads();
    pass_store(v, t, tw_p2, sre, sim);  __syncthreads();
    load_p3(v, t, sre, sim);            __syncthreads();
    p3_store(v, t, g_m2, sre, sim);     __syncthreads();

    // FFT #3 (pass 3 fuses *m3 and the bin-0 reduction of "FFT #4")
    load_p1(v, t, sre, sim);            __syncthreads();
    pass_store(v, t, tw_p1, sre, sim);  __syncthreads();
    load_p2(v, t, sre, sim);            __syncthreads();
    pass_store(v, t, tw_p2, sre, sim);  __syncthreads();
    load_p3(v, t, sre, sim);            __syncthreads();

    float2 acc = make_float2(0.f, 0.f);
#pragma unroll
    for (int i = 0; i < 2; i++) {
        int q = t + TPB * i;
        float2 o[8];
        dft8(v + 8 * i, o);
#pragma unroll
        for (int d = 0; d < 8; d++) {
            int g = q + 256 * d;
            float2 val = cmul(o[d], g_m3[g]);
            acc.x += val.x;
            acc.y += val.y;
        }
    }
    // warp reduce
#pragma unroll
    for (int off = 16; off > 0; off >>= 1) {
        acc.x += __shfl_xor_sync(0xffffffffu, acc.x, off);
        acc.y += __shfl_xor_sync(0xffffffffu, acc.y, off);
    }
    if ((t & 31) == 0) { sre[t >> 5] = acc.x; sim[t >> 5] = acc.y; }
    __syncthreads();
    if (t == 0) {
        float Sx = sre[0] + sre[1] + sre[2] + sre[3];
        float Sy = sim[0] + sim[1] + sim[2] + sim[3];
        // angle(sum * e^{i w310}) then exact triangular wrap == asin(sin(.))
        float th = atan2f(Sy, Sx) + w[14336];
        const float PI_F = 3.14159265358979323846f;
        const float HPI  = 1.57079632679489661923f;
        if (th >  HPI) th =  PI_F - th;
        else if (th < -HPI) th = -PI_F - th;
        out[blockIdx.x] = th;
    }
}

// ---------------------------------------------------------------- launch
extern "C" void kernel_launch(void* const* d_in, const int* in_sizes, int n_in,
                              void* d_out, int out_size) {
    const float* x = (const float*)d_in[0];
    const float* w = (const float*)d_in[1];
    float* out = (float*)d_out;
    int rows = in_sizes[0] / NFFT;

    init_tables_kernel<<<(NFFT + 255) / 256, 256>>>(w);
    phasor_kernel<<<rows, TPB>>>(x, w, out);
}

// round 2
// speedup vs baseline: 1.4043x; 1.4043x over previous
#include <cuda_runtime.h>

// ============================================================================
// PhasorTransformer: 16384 rows x 2048.
// z=exp(i(x+w00)); [FFT2048; *m_b] x3 ; final FFT needed only at bin 0 -> sum.
// ortho scalings dropped (angle-invariant). out = triangular wrap of angle+w310.
//
// FFT2048 = radix 16*16*8, 128 thr/row, 16 complex regs/thread, 3 smem passes.
// R2 changes vs R1:
//   - double-buffered smem: 17 syncthreads -> 9
//   - twiddle powers via depth-4 tree (was 15-deep serial cmul chain)
//   - __launch_bounds__(128,4) -> 4 CTAs/SM (was reg-limited to 3)
//   - __sincosf for the input phasor (small-range args, plenty of margin)
// ============================================================================

#define NFFT 2048
#define TPB  128
#define PADI(i) ((i) + ((i) >> 5))

__device__ float2 g_m1[NFFT];
__device__ float2 g_m2[NFFT];
__device__ float2 g_m3[NFFT];
__device__ float2 g_tw[NFFT];

__global__ void init_tables_kernel(const float* __restrict__ w) {
    int k = blockIdx.x * blockDim.x + threadIdx.x;
    if (k >= NFFT) return;
    double a;
    a = (double)w[2048 + k] + (double)w[4096 + k];
    g_m1[k] = make_float2((float)cos(a), (float)sin(a));
    a = (double)w[6144 + k] + (double)w[8192 + k];
    g_m2[k] = make_float2((float)cos(a), (float)sin(a));
    a = (double)w[10240 + k] + (double)w[12288 + k];
    g_m3[k] = make_float2((float)cos(a), (float)sin(a));
    double t = -6.283185307179586476925286766559 * (double)k / (double)NFFT;
    g_tw[k] = make_float2((float)cos(t), (float)sin(t));
}

__device__ __forceinline__ float2 cmul(float2 a, float2 b) {
    return make_float2(fmaf(a.x, b.x, -a.y * b.y), fmaf(a.x, b.y, a.y * b.x));
}
__device__ __forceinline__ float2 cadd(float2 a, float2 b) { return make_float2(a.x + b.x, a.y + b.y); }
__device__ __forceinline__ float2 csub(float2 a, float2 b) { return make_float2(a.x - b.x, a.y - b.y); }
__device__ __forceinline__ float2 mulnegi(float2 a) { return make_float2(a.y, -a.x); }

__device__ __forceinline__ void dft4(float2& a0, float2& a1, float2& a2, float2& a3) {
    float2 t0 = cadd(a0, a2), t1 = csub(a0, a2);
    float2 t2 = cadd(a1, a3), t3 = csub(a1, a3);
    a0 = cadd(t0, t2);
    a2 = csub(t0, t2);
    float2 it3 = mulnegi(t3);
    a1 = cadd(t1, it3);
    a3 = csub(t1, it3);
}

// forward DFT16 (DIF 4x4). Output X[k1+4*k2] at v[4*k1+k2].
__device__ __forceinline__ void dft16(float2 v[16]) {
    const float C1 = 0.92387953251128675f;
    const float S1 = 0.38268343236508977f;
    const float R2 = 0.70710678118654752f;
#pragma unroll
    for (int j2 = 0; j2 < 4; j2++)
        dft4(v[j2], v[j2 + 4], v[j2 + 8], v[j2 + 12]);
    v[5]  = cmul(v[5],  make_float2( C1, -S1));
    v[9]  = cmul(v[9],  make_float2( R2, -R2));
    v[13] = cmul(v[13], make_float2( S1, -C1));
    v[6]  = cmul(v[6],  make_float2( R2, -R2));
    v[10] = mulnegi(v[10]);
    v[14] = cmul(v[14], make_float2(-R2, -R2));
    v[7]  = cmul(v[7],  make_float2( S1, -C1));
    v[11] = cmul(v[11], make_float2(-R2, -R2));
    v[15] = cmul(v[15], make_float2(-C1,  S1));
#pragma unroll
    for (int k1 = 0; k1 < 4; k1++)
        dft4(v[4 * k1], v[4 * k1 + 1], v[4 * k1 + 2], v[4 * k1 + 3]);
}

__device__ __forceinline__ void dft8(float2* a, float2* o) {
    const float R2 = 0.70710678118654752f;
    dft4(a[0], a[2], a[4], a[6]);
    dft4(a[1], a[3], a[5], a[7]);
    a[3] = cmul(a[3], make_float2(R2, -R2));
    a[5] = mulnegi(a[5]);
    a[7] = cmul(a[7], make_float2(-R2, -R2));
#pragma unroll
    for (int k1 = 0; k1 < 4; k1++) {
        o[k1]     = cadd(a[2 * k1], a[2 * k1 + 1]);
        o[k1 + 4] = csub(a[2 * k1], a[2 * k1 + 1]);
    }
}

// dft16 + outer twiddle w1^f + store at dst[f*128+t].
// Twiddle powers via depth-4 tree (no serial chain).
__device__ __forceinline__ void pass_store(float2 v[16], int t, float2 w1,
                                           float* dre, float* dim) {
    dft16(v);
    float2 tw[16];
    tw[1] = w1;
    tw[2] = cmul(tw[1], tw[1]);
    tw[3] = cmul(tw[2], tw[1]);
    tw[4] = cmul(tw[2], tw[2]);
    tw[5] = cmul(tw[4], tw[1]);
    tw[6] = cmul(tw[4], tw[2]);
    tw[7] = cmul(tw[4], tw[3]);
    tw[8] = cmul(tw[4], tw[4]);
#pragma unroll
    for (int f = 9; f < 16; f++) tw[f] = cmul(tw[8], tw[f - 8]);

    constexpr int idx16[16] = {0, 4, 8, 12, 1, 5, 9, 13, 2, 6, 10, 14, 3, 7, 11, 15};
    {
        int a = PADI(t);
        dre[a] = v[0].x; dim[a] = v[0].y;
    }
#pragma unroll
    for (int f = 1; f < 16; f++) {
        float2 val = cmul(v[idx16[f]], tw[f]);
        int a = PADI(f * TPB + t);
        dre[a] = val.x; dim[a] = val.y;
    }
}

__device__ __forceinline__ void load_p1(float2 v[16], int t,
                                        const float* sre, const float* sim) {
#pragma unroll
    for (int j = 0; j < 16; j++) {
        int a = PADI(t + TPB * j);
        v[j] = make_float2(sre[a], sim[a]);
    }
}

__device__ __forceinline__ void load_p2(float2 v[16], int t,
                                        const float* sre, const float* sim) {
    int base = (t >> 3) * TPB + (t & 7);
#pragma unroll
    for (int j = 0; j < 16; j++) {
        int a = PADI(base + 8 * j);
        v[j] = make_float2(sre[a], sim[a]);
    }
}

__device__ __forceinline__ void load_p3(float2 v[16], int t,
                                        const float* sre, const float* sim) {
#pragma unroll
    for (int i = 0; i < 2; i++) {
        int q = t + TPB * i;
#pragma unroll
        for (int j = 0; j < 8; j++) {
            int a = PADI(q * 8 + j);
            v[8 * i + j] = make_float2(sre[a], sim[a]);
        }
    }
}

__device__ __forceinline__ void p3_store(float2 v[16], int t, const float2* __restrict__ m,
                                         float* dre, float* dim) {
#pragma unroll
    for (int i = 0; i < 2; i++) {
        int q = t + TPB * i;
        float2 o[8];
        dft8(v + 8 * i, o);
#pragma unroll
        for (int d = 0; d < 8; d++) {
            int g = q + 256 * d;
            float2 val = cmul(o[d], m[g]);
            int a = PADI(g);
            dre[a] = val.x; dim[a] = val.y;
        }
    }
}

// ---------------------------------------------------------------- main kernel
__global__ void __launch_bounds__(TPB, 4)
phasor_kernel(const float* __restrict__ x, const float* __restrict__ w,
              float* __restrict__ out) {
    __shared__ float Are[2112], Aim[2112];
    __shared__ float Bre[2112], Bim[2112];
    const int t = threadIdx.x;

    float2 v[16];

    // input phasor: z = exp(i(x + w00))
    {
        const float* xr = x + (size_t)blockIdx.x * NFFT;
#pragma unroll
        for (int j = 0; j < 16; j++) {
            int e = t + TPB * j;
            float ph = xr[e] + w[e];
            float s, c;
            __sincosf(ph, &s, &c);
            v[j] = make_float2(c, s);
        }
    }
    const float2 tw_p1 = g_tw[t];
    const float2 tw_p2 = g_tw[16 * (t & 7)];

    // FFT #1:  regs -> A -> B -> A
    pass_store(v, t, tw_p1, Are, Aim);                       __syncthreads();
    load_p2(v, t, Are, Aim); pass_store(v, t, tw_p2, Bre, Bim); __syncthreads();
    load_p3(v, t, Bre, Bim); p3_store(v, t, g_m1, Are, Aim);    __syncthreads();

    // FFT #2:  A -> B -> A -> B
    load_p1(v, t, Are, Aim); pass_store(v, t, tw_p1, Bre, Bim); __syncthreads();
    load_p2(v, t, Bre, Bim); pass_store(v, t, tw_p2, Are, Aim); __syncthreads();
    load_p3(v, t, Are, Aim); p3_store(v, t, g_m2, Bre, Bim);    __syncthreads();

    // FFT #3:  B -> A -> B -> (accumulate)
    load_p1(v, t, Bre, Bim); pass_store(v, t, tw_p1, Are, Aim); __syncthreads();
    load_p2(v, t, Are, Aim); pass_store(v, t, tw_p2, Bre, Bim); __syncthreads();
    load_p3(v, t, Bre, Bim);

    float2 acc = make_float2(0.f, 0.f);
#pragma unroll
    for (int i = 0; i < 2; i++) {
        int q = t + TPB * i;
        float2 o[8];
        dft8(v + 8 * i, o);
#pragma unroll
        for (int d = 0; d < 8; d++) {
            int g = q + 256 * d;
            float2 val = cmul(o[d], g_m3[g]);
            acc.x += val.x;
            acc.y += val.y;
        }
    }
#pragma unroll
    for (int off = 16; off > 0; off >>= 1) {
        acc.x += __shfl_xor_sync(0xffffffffu, acc.x, off);
        acc.y += __shfl_xor_sync(0xffffffffu, acc.y, off);
    }
    // A is idle here (last written in FFT3 pass2 path? -> last write to A was
    // FFT3 pass_store->A at step 7, fully consumed by load_p2 before the sync
    // at step 8; safe to reuse after one more sync).
    __syncthreads();
    if ((t & 31) == 0) { Are[t >> 5] = acc.x; Aim[t >> 5] = acc.y; }
    __syncthreads();
    if (t == 0) {
        float Sx = Are[0] + Are[1] + Are[2] + Are[3];
        float Sy = Aim[0] + Aim[1] + Aim[2] + Aim[3];
        float th = atan2f(Sy, Sx) + w[14336];
        const float PI_F = 3.14159265358979323846f;
        const float HPI  = 1.57079632679489661923f;
        if (th >  HPI) th =  PI_F - th;
        else if (th < -HPI) th = -PI_F - th;
        out[blockIdx.x] = th;
    }
}

extern "C" void kernel_launch(void* const* d_in, const int* in_sizes, int n_in,
                              void* d_out, int out_size) {
    const float* x = (const float*)d_in[0];
    const float* w = (const float*)d_in[1];
    float* out = (float*)d_out;
    int rows = in_sizes[0] / NFFT;

    init_tables_kernel<<<(NFFT + 255) / 256, 256>>>(w);
    phasor_kernel<<<rows, TPB>>>(x, w, out);
}

// round 5
// speedup vs baseline: 7.9726x; 5.6771x over previous
#include <cuda_runtime.h>
#include <math.h>

// ============================================================================
// PhasorTransformer, linear-algebra collapsed form.
//
// Reference: z = exp(i(x+w00)); 4x [ FFT ; diag phase ] ; out = asin(sin(angle(z[0]))).
// Everything after forming z is linear and only bin 0 is read at the end:
//   zf[0] = e^{i w31[0]} * sum_t e^{i w00[t]} * r[t] * e^{i x[t]},
//   r = F(m1 .* F(m2 .* F(m3))),   m1=e^{i(w01+w10)}, m2=e^{i(w11+w20)},
//   m3=e^{i(w21+w30)}   (F unnormalized DFT; F^T=F; ortho scalings are
//   positive reals -> drop out of angle; asin(sin) = exact triangular wrap).
//
// Kernel 1 (1 block x 256 thr): build r'' (= r with w00 and w31[0] folded in)
//   via 3 Stockham radix-2 FFTs in shared memory, tables in double precision.
// Kernel 2: batched complex dot, warp-per-row, r'' in smem, float4 loads,
//   __sincosf, warp-shuffle reduce. DRAM/MUFU co-bound.
// ============================================================================

#define NFFT 2048

__device__ float g_rre[NFFT];
__device__ float g_rim[NFFT];

// ---------------------------------------------------------------- precompute
#define PRE_T 256

__global__ void __launch_bounds__(PRE_T)
precompute_kernel(const float* __restrict__ w) {
    // ping-pong buffers [2][2048] for re and im + twiddle table
    __shared__ float br[2][NFFT];
    __shared__ float bi[2][NFFT];
    __shared__ float twr[NFFT / 2];
    __shared__ float twi[NFFT / 2];
    const int tid = threadIdx.x;

    // twiddles exp(-2*pi*i*k/2048), k < 1024, in double
    for (int k = tid; k < NFFT / 2; k += PRE_T) {
        double a = -6.283185307179586476925286766559 * (double)k / (double)NFFT;
        double s, c;
        sincos(a, &s, &c);
        twr[k] = (float)c;
        twi[k] = (float)s;
    }
    // buffer 0 = m3 = exp(i(w21 + w30))
    for (int e = tid; e < NFFT; e += PRE_T) {
        double a = (double)w[10240 + e] + (double)w[12288 + e];
        double s, c;
        sincos(a, &s, &c);
        br[0][e] = (float)c;
        bi[0][e] = (float)s;
    }
    __syncthreads();

    int cur = 0;
    for (int f = 0; f < 3; f++) {
        // 11 Stockham stages: natural-order output
        for (int t = 0; t < 11; t++) {
            const int s = 1 << t;
            const int nxt = cur ^ 1;
            for (int n = tid; n < NFFT / 2; n += PRE_T) {
                const int p = n >> t;
                const int q = n & (s - 1);
                const int j0 = q + (p << (t + 1));
                const int j1 = j0 + s;
                float ar = br[cur][n],            ai = bi[cur][n];
                float cr = br[cur][n + NFFT / 2], ci = bi[cur][n + NFFT / 2];
                br[nxt][j0] = ar + cr;
                bi[nxt][j0] = ai + ci;
                float dr = ar - cr, di = ai - ci;
                float wr = twr[p << t], wi = twi[p << t];
                br[nxt][j1] = fmaf(dr, wr, -di * wi);
                bi[nxt][j1] = fmaf(dr, wi,  di * wr);
            }
            cur = nxt;
            __syncthreads();
        }
        // inter-FFT phase multiply (f=0: m2, f=1: m1, f=2: fold w00 + w31[0])
        if (f < 2) {
            const int o1 = (f == 0) ? 6144 : 2048;
            const int o2 = (f == 0) ? 8192 : 4096;
            for (int e = tid; e < NFFT; e += PRE_T) {
                double a = (double)w[o1 + e] + (double)w[o2 + e];
                double s, c;
                sincos(a, &s, &c);
                float cr = (float)c, ci = (float)s;
                float vr = br[cur][e], vi = bi[cur][e];
                br[cur][e] = fmaf(vr, cr, -vi * ci);
                bi[cur][e] = fmaf(vr, ci,  vi * cr);
            }
            __syncthreads();
        }
    }

    const double w310 = (double)w[14336];
    for (int e = tid; e < NFFT; e += PRE_T) {
        double a = (double)w[e] + w310;
        double s, c;
        sincos(a, &s, &c);
        float cr = (float)c, ci = (float)s;
        float vr = br[cur][e], vi = bi[cur][e];
        g_rre[e] = fmaf(vr, cr, -vi * ci);
        g_rim[e] = fmaf(vr, ci,  vi * cr);
    }
}

// ---------------------------------------------------------------- main kernel
// warp-per-row complex dot product: S = sum_t r''[t] e^{i x[t]}
#define TPB 512
#define WPB (TPB / 32)

__global__ void __launch_bounds__(TPB)
dot_kernel(const float* __restrict__ x, float* __restrict__ out, int rows) {
    __shared__ float sR[NFFT], sI[NFFT];
    const int tid = threadIdx.x;
    for (int i = tid; i < NFFT; i += TPB) {
        sR[i] = g_rre[i];
        sI[i] = g_rim[i];
    }
    __syncthreads();

    const int warp = tid >> 5;
    const int lane = tid & 31;
    const float4* sR4 = (const float4*)sR;
    const float4* sI4 = (const float4*)sI;

    for (int row = blockIdx.x * WPB + warp; row < rows; row += gridDim.x * WPB) {
        const float4* xr = (const float4*)(x + (size_t)row * NFFT);
        float ax = 0.f, ay = 0.f;
#pragma unroll
        for (int j = 0; j < 16; j++) {
            int e4 = lane + 32 * j;            // float4 index (512 per row)
            float4 xv = __ldg(&xr[e4]);
            float4 rr = sR4[e4];
            float4 ri = sI4[e4];
            float s, c;
            __sincosf(xv.x, &s, &c);
            ax = fmaf(rr.x, c, ax); ax = fmaf(-ri.x, s, ax);
            ay = fmaf(rr.x, s, ay); ay = fmaf( ri.x, c, ay);
            __sincosf(xv.y, &s, &c);
            ax = fmaf(rr.y, c, ax); ax = fmaf(-ri.y, s, ax);
            ay = fmaf(rr.y, s, ay); ay = fmaf( ri.y, c, ay);
            __sincosf(xv.z, &s, &c);
            ax = fmaf(rr.z, c, ax); ax = fmaf(-ri.z, s, ax);
            ay = fmaf(rr.z, s, ay); ay = fmaf( ri.z, c, ay);
            __sincosf(xv.w, &s, &c);
            ax = fmaf(rr.w, c, ax); ax = fmaf(-ri.w, s, ax);
            ay = fmaf(rr.w, s, ay); ay = fmaf( ri.w, c, ay);
        }
#pragma unroll
        for (int off = 16; off > 0; off >>= 1) {
            ax += __shfl_xor_sync(0xffffffffu, ax, off);
            ay += __shfl_xor_sync(0xffffffffu, ay, off);
        }
        if (lane == 0) {
            float th = atan2f(ay, ax);
            const float PI_F = 3.14159265358979323846f;
            const float HPI  = 1.57079632679489661923f;
            if (th >  HPI)      th =  PI_F - th;
            else if (th < -HPI) th = -PI_F - th;
            out[row] = th;
        }
    }
}

// ---------------------------------------------------------------- launch
extern "C" void kernel_launch(void* const* d_in, const int* in_sizes, int n_in,
                              void* d_out, int out_size) {
    const float* x = (const float*)d_in[0];
    const float* w = (const float*)d_in[1];
    float* out = (float*)d_out;
    const int rows = in_sizes[0] / NFFT;
    if (rows <= 0) return;

    precompute_kernel<<<1, PRE_T>>>(w);

    int grid = (rows + WPB - 1) / WPB;     // one row per warp per pass
    dot_kernel<<<grid, TPB>>>(x, out, rows);
}

// round 6
// speedup vs baseline: 12.4813x; 1.5655x over previous
#include <cuda_runtime.h>
#include <math.h>

// ============================================================================
// PhasorTransformer, linear-algebra collapsed form.
//
// zf[0] = e^{i w31[0]} * sum_t e^{i w00[t]} * r[t] * e^{i x[t]},
//   r = F(m1 .* F(m2 .* F(m3))),  m1=e^{i(w01+w10)}, m2=e^{i(w11+w20)},
//   m3=e^{i(w21+w30)}   (F unnormalized DFT, F^T=F; ortho scalings drop out of
//   the angle; asin(sin) = exact triangular wrap).
//
// R6 changes: precompute all-float (sincosf; args are all < pi so no slow
// range reduction), 1024 threads; dot kernel TPB 256 for higher occupancy and
// __ldcs streaming loads of x.
// ============================================================================

#define NFFT 2048

__device__ float g_rre[NFFT];
__device__ float g_rim[NFFT];

// ---------------------------------------------------------------- precompute
#define PRE_T 1024

__global__ void __launch_bounds__(PRE_T)
precompute_kernel(const float* __restrict__ w) {
    __shared__ float br[2][NFFT];
    __shared__ float bi[2][NFFT];
    __shared__ float twr[NFFT / 2];
    __shared__ float twi[NFFT / 2];
    const int tid = threadIdx.x;

    // twiddles exp(-2*pi*i*k/2048), k < 1024; arg in (-pi, 0] -> fast sincosf
    {
        float a = -6.2831853071795864769f * (float)tid / (float)NFFT;
        float s, c;
        sincosf(a, &s, &c);
        twr[tid] = c;
        twi[tid] = s;
    }
    // buffer 0 = m3 = exp(i(w21 + w30)); |arg| <= 2*pi/10
#pragma unroll
    for (int k = 0; k < 2; k++) {
        int e = tid + PRE_T * k;
        float a = w[10240 + e] + w[12288 + e];
        float s, c;
        sincosf(a, &s, &c);
        br[0][e] = c;
        bi[0][e] = s;
    }
    __syncthreads();

    int cur = 0;
    for (int f = 0; f < 3; f++) {
        // 11 Stockham DIF stages, natural-order output, 1 butterfly/thread
        for (int t = 0; t < 11; t++) {
            const int s = 1 << t;
            const int nxt = cur ^ 1;
            const int n = tid;
            const int p = n >> t;
            const int q = n & (s - 1);
            const int j0 = q + (p << (t + 1));
            const int j1 = j0 + s;
            float ar = br[cur][n],            ai = bi[cur][n];
            float crr = br[cur][n + NFFT / 2], cii = bi[cur][n + NFFT / 2];
            float sr = ar + crr, si = ai + cii;
            float dr = ar - crr, di = ai - cii;
            float wr = twr[p << t], wi = twi[p << t];
            float er = fmaf(dr, wr, -di * wi);
            float ei = fmaf(dr, wi,  di * wr);
            br[nxt][j0] = sr; bi[nxt][j0] = si;
            br[nxt][j1] = er; bi[nxt][j1] = ei;
            cur = nxt;
            __syncthreads();
        }
        if (f < 2) {
            const int o1 = (f == 0) ? 6144 : 2048;
            const int o2 = (f == 0) ? 8192 : 4096;
#pragma unroll
            for (int k = 0; k < 2; k++) {
                int e = tid + PRE_T * k;
                float a = w[o1 + e] + w[o2 + e];
                float s, c;
                sincosf(a, &s, &c);
                float vr = br[cur][e], vi = bi[cur][e];
                br[cur][e] = fmaf(vr, c, -vi * s);
                bi[cur][e] = fmaf(vr, s,  vi * c);
            }
            __syncthreads();
        }
    }

    const float w310 = w[14336];
#pragma unroll
    for (int k = 0; k < 2; k++) {
        int e = tid + PRE_T * k;
        float a = w[e] + w310;
        float s, c;
        sincosf(a, &s, &c);
        float vr = br[cur][e], vi = bi[cur][e];
        g_rre[e] = fmaf(vr, c, -vi * s);
        g_rim[e] = fmaf(vr, s,  vi * c);
    }
}

// ---------------------------------------------------------------- main kernel
// warp-per-row complex dot product: S = sum_t r''[t] e^{i x[t]}
#define TPB 256
#define WPB (TPB / 32)

__global__ void __launch_bounds__(TPB)
dot_kernel(const float* __restrict__ x, float* __restrict__ out, int rows) {
    __shared__ float sR[NFFT], sI[NFFT];
    const int tid = threadIdx.x;
    for (int i = tid; i < NFFT; i += TPB) {
        sR[i] = g_rre[i];
        sI[i] = g_rim[i];
    }
    __syncthreads();

    const int warp = tid >> 5;
    const int lane = tid & 31;
    const float4* sR4 = (const float4*)sR;
    const float4* sI4 = (const float4*)sI;

    for (int row = blockIdx.x * WPB + warp; row < rows; row += gridDim.x * WPB) {
        const float4* xr = (const float4*)(x + (size_t)row * NFFT);
        float ax = 0.f, ay = 0.f;
#pragma unroll
        for (int j = 0; j < 16; j++) {
            int e4 = lane + 32 * j;              // float4 index (512 per row)
            float4 xv = __ldcs(&xr[e4]);         // streaming: read-once data
            float4 rr = sR4[e4];
            float4 ri = sI4[e4];
            float s, c;
            __sincosf(xv.x, &s, &c);
            ax = fmaf(rr.x, c, ax); ax = fmaf(-ri.x, s, ax);
            ay = fmaf(rr.x, s, ay); ay = fmaf( ri.x, c, ay);
            __sincosf(xv.y, &s, &c);
            ax = fmaf(rr.y, c, ax); ax = fmaf(-ri.y, s, ax);
            ay = fmaf(rr.y, s, ay); ay = fmaf( ri.y, c, ay);
            __sincosf(xv.z, &s, &c);
            ax = fmaf(rr.z, c, ax); ax = fmaf(-ri.z, s, ax);
            ay = fmaf(rr.z, s, ay); ay = fmaf( ri.z, c, ay);
            __sincosf(xv.w, &s, &c);
            ax = fmaf(rr.w, c, ax); ax = fmaf(-ri.w, s, ax);
            ay = fmaf(rr.w, s, ay); ay = fmaf( ri.w, c, ay);
        }
#pragma unroll
        for (int off = 16; off > 0; off >>= 1) {
            ax += __shfl_xor_sync(0xffffffffu, ax, off);
            ay += __shfl_xor_sync(0xffffffffu, ay, off);
        }
        if (lane == 0) {
            float th = atan2f(ay, ax);
            const float PI_F = 3.14159265358979323846f;
            const float HPI  = 1.57079632679489661923f;
            if (th >  HPI)      th =  PI_F - th;
            else if (th < -HPI) th = -PI_F - th;
            out[row] = th;
        }
    }
}

// ---------------------------------------------------------------- launch
extern "C" void kernel_launch(void* const* d_in, const int* in_sizes, int n_in,
                              void* d_out, int out_size) {
    const float* x = (const float*)d_in[0];
    const float* w = (const float*)d_in[1];
    float* out = (float*)d_out;
    const int rows = in_sizes[0] / NFFT;
    if (rows <= 0) return;

    precompute_kernel<<<1, PRE_T>>>(w);

    int grid = (rows + WPB - 1) / WPB;     // one row per warp
    dot_kernel<<<grid, TPB>>>(x, out, rows);
}